// round 1
// baseline (speedup 1.0000x reference)
#include <cuda_runtime.h>
#include <cuda_bf16.h>
#include <cstdint>

// Problem constants (fixed by the reference)
#define N_NODES  50000
#define N_EDGES  800000
#define HIDDEN   128
#define N_GRAPHS 512

// ---------------------------------------------------------------------------
// Static device scratch (allocation-free per harness rules)
// ---------------------------------------------------------------------------
__device__ float g_dinv[N_NODES];            // degree accumulator -> dinv (in place)
__device__ float g_p1[(size_t)N_NODES * HIDDEN];   // layer-1 pre-scaled features
__device__ float g_p2[(size_t)N_NODES * HIDDEN];   // layer-2 pre-scaled features
__device__ float g_acc[(size_t)N_NODES * HIDDEN];  // scatter accumulator (reused)
__device__ float g_pool[N_GRAPHS];
__device__ float g_cnt[N_GRAPHS];

// ---------------------------------------------------------------------------
// Zeroing kernels (pure kernel launches keep graph capture trivially legal)
// ---------------------------------------------------------------------------
__global__ void zero_small_kernel() {
    int i = blockIdx.x * blockDim.x + threadIdx.x;
    if (i < N_NODES) g_dinv[i] = 0.0f;
    if (i < N_GRAPHS) { g_pool[i] = 0.0f; g_cnt[i] = 0.0f; }
}

__global__ void zero_acc_kernel() {
    int i = blockIdx.x * blockDim.x + threadIdx.x;   // float4 index
    if (i < N_NODES * (HIDDEN / 4)) {
        float4 z = make_float4(0.f, 0.f, 0.f, 0.f);
        reinterpret_cast<float4*>(g_acc)[i] = z;
    }
}

// ---------------------------------------------------------------------------
// Degree + dinv
// ---------------------------------------------------------------------------
__global__ void deg_kernel(const int* __restrict__ dst) {
    int e = blockIdx.x * blockDim.x + threadIdx.x;
    if (e < N_EDGES) atomicAdd(&g_dinv[dst[e]], 1.0f);
}

__global__ void dinv_kernel() {
    int i = blockIdx.x * blockDim.x + threadIdx.x;
    if (i < N_NODES) g_dinv[i] = rsqrtf(g_dinv[i] + 1.0f);
}

// ---------------------------------------------------------------------------
// GEMM: P_out[row] = (in[row] @ W) * dinv[row]
//   MODE 0: in = X (raw input), write g_p1
//   MODE 1: in = relu(dinv*(g_acc + g_p1) + b)  (fused layer-1 epilogue), write g_p2
// Block: 256 threads (8 warps), tile = 64 rows. Each warp handles 8 rows;
// lane l owns columns [4l, 4l+4). W (64 KB) + X tile (32 KB) in dynamic smem.
// ---------------------------------------------------------------------------
#define GEMM_SMEM_BYTES ((16384 + 8192 + 128) * 4)

template <int MODE>
__global__ void gemm_kernel(const float* __restrict__ X,
                            const float* __restrict__ W,
                            const float* __restrict__ bias) {
    extern __shared__ float smem[];
    float* Ws  = smem;                 // 128*128
    float* Xs  = smem + 16384;         // 64*128
    float* bsh = smem + 16384 + 8192;  // 128

    const int tid = threadIdx.x;

    // Load W into smem (4096 float4 across 256 threads)
    const float4* W4 = reinterpret_cast<const float4*>(W);
    float4* Ws4 = reinterpret_cast<float4*>(Ws);
    #pragma unroll
    for (int i = tid; i < 4096; i += 256) Ws4[i] = W4[i];
    if (MODE == 1 && tid < 128) bsh[tid] = bias[tid];
    __syncthreads();

    const int row0 = blockIdx.x * 64;

    // Stage 64 input rows into smem (with fused layer-1 epilogue for MODE 1)
    for (int i = tid; i < 2048; i += 256) {     // 2048 float4 = 64 rows * 32
        int r = i >> 5, seg = i & 31;
        int row = row0 + r;
        float4 v = make_float4(0.f, 0.f, 0.f, 0.f);
        if (row < N_NODES) {
            if (MODE == 0) {
                v = reinterpret_cast<const float4*>(X + (size_t)row * HIDDEN)[seg];
            } else {
                float4 a = reinterpret_cast<const float4*>(g_acc + (size_t)row * HIDDEN)[seg];
                float4 p = reinterpret_cast<const float4*>(g_p1  + (size_t)row * HIDDEN)[seg];
                float4 b = reinterpret_cast<const float4*>(bsh)[seg];
                float di = g_dinv[row];
                v.x = fmaxf(di * (a.x + p.x) + b.x, 0.f);
                v.y = fmaxf(di * (a.y + p.y) + b.y, 0.f);
                v.z = fmaxf(di * (a.z + p.z) + b.z, 0.f);
                v.w = fmaxf(di * (a.w + p.w) + b.w, 0.f);
            }
        }
        reinterpret_cast<float4*>(Xs + r * HIDDEN)[seg] = v;
    }
    __syncthreads();

    const int w = tid >> 5, l = tid & 31;
    const int rbase = w * 8;

    float4 acc[8];
    #pragma unroll
    for (int r = 0; r < 8; r++) acc[r] = make_float4(0.f, 0.f, 0.f, 0.f);

    const float4* Ws4c = reinterpret_cast<const float4*>(Ws);
    #pragma unroll 4
    for (int k4 = 0; k4 < 32; k4++) {
        float4 w0 = Ws4c[(4 * k4 + 0) * 32 + l];
        float4 w1 = Ws4c[(4 * k4 + 1) * 32 + l];
        float4 w2 = Ws4c[(4 * k4 + 2) * 32 + l];
        float4 w3 = Ws4c[(4 * k4 + 3) * 32 + l];
        #pragma unroll
        for (int r = 0; r < 8; r++) {
            float4 xq = reinterpret_cast<const float4*>(Xs + (rbase + r) * HIDDEN)[k4];
            acc[r].x += xq.x * w0.x + xq.y * w1.x + xq.z * w2.x + xq.w * w3.x;
            acc[r].y += xq.x * w0.y + xq.y * w1.y + xq.z * w2.y + xq.w * w3.y;
            acc[r].z += xq.x * w0.z + xq.y * w1.z + xq.z * w2.z + xq.w * w3.z;
            acc[r].w += xq.x * w0.w + xq.y * w1.w + xq.z * w2.w + xq.w * w3.w;
        }
    }

    float* Pout = (MODE == 0) ? g_p1 : g_p2;
    #pragma unroll
    for (int r = 0; r < 8; r++) {
        int row = row0 + rbase + r;
        if (row < N_NODES) {
            float di = g_dinv[row];
            float4 o = make_float4(acc[r].x * di, acc[r].y * di, acc[r].z * di, acc[r].w * di);
            reinterpret_cast<float4*>(Pout + (size_t)row * HIDDEN)[l] = o;
        }
    }
}

// ---------------------------------------------------------------------------
// Scatter: g_acc[dst] += P[src]. One warp per edge; lane l owns float4 at 4l.
// red.global.add.v4.f32 = one vector reduction per lane (sm_90+).
// ---------------------------------------------------------------------------
__global__ void scatter_kernel(const int* __restrict__ src,
                               const int* __restrict__ dst,
                               int use_p2) {
    int t = blockIdx.x * blockDim.x + threadIdx.x;
    int e = t >> 5;
    int l = t & 31;
    if (e >= N_EDGES) return;
    int s = __ldg(&src[e]);
    int d = __ldg(&dst[e]);
    const float* P = use_p2 ? g_p2 : g_p1;
    float4 v = __ldg(reinterpret_cast<const float4*>(P + (size_t)s * HIDDEN) + l);
    float* a = g_acc + (size_t)d * HIDDEN + 4 * l;
    asm volatile("red.global.add.v4.f32 [%0], {%1, %2, %3, %4};"
                 :: "l"(a), "f"(v.x), "f"(v.y), "f"(v.z), "f"(v.w)
                 : "memory");
}

// ---------------------------------------------------------------------------
// Final: per-node h2 = relu(dinv*(acc+p2)+b2); s = dot(h2, Wl);
// atomic-accumulate into per-graph bins. One warp per node.
// ---------------------------------------------------------------------------
__global__ void final_kernel(const float* __restrict__ b2,
                             const float* __restrict__ Wl,
                             const int* __restrict__ batch) {
    int t = blockIdx.x * blockDim.x + threadIdx.x;
    int n = t >> 5;
    int l = t & 31;
    if (n >= N_NODES) return;
    float di = g_dinv[n];
    float4 a  = __ldg(reinterpret_cast<const float4*>(g_acc + (size_t)n * HIDDEN) + l);
    float4 p  = __ldg(reinterpret_cast<const float4*>(g_p2  + (size_t)n * HIDDEN) + l);
    float4 b  = __ldg(reinterpret_cast<const float4*>(b2) + l);
    float4 wl = __ldg(reinterpret_cast<const float4*>(Wl) + l);
    float h0 = fmaxf(di * (a.x + p.x) + b.x, 0.f);
    float h1 = fmaxf(di * (a.y + p.y) + b.y, 0.f);
    float h2 = fmaxf(di * (a.z + p.z) + b.z, 0.f);
    float h3 = fmaxf(di * (a.w + p.w) + b.w, 0.f);
    float s = h0 * wl.x + h1 * wl.y + h2 * wl.z + h3 * wl.w;
    #pragma unroll
    for (int off = 16; off; off >>= 1) s += __shfl_xor_sync(0xffffffffu, s, off);
    if (l == 0) {
        int g = __ldg(&batch[n]);
        atomicAdd(&g_pool[g], s);
        atomicAdd(&g_cnt[g], 1.0f);
    }
}

__global__ void out_kernel(float* __restrict__ out, const float* __restrict__ bl) {
    int g = blockIdx.x * blockDim.x + threadIdx.x;
    if (g < N_GRAPHS) out[g] = g_pool[g] / fmaxf(g_cnt[g], 1.0f) + bl[0];
}

// ---------------------------------------------------------------------------
// Launch
// ---------------------------------------------------------------------------
extern "C" void kernel_launch(void* const* d_in, const int* in_sizes, int n_in,
                              void* d_out, int out_size) {
    const float* x     = (const float*)d_in[0];
    const int*   ei    = (const int*)  d_in[1];
    const int*   batch = (const int*)  d_in[2];
    const float* W1    = (const float*)d_in[3];
    const float* b1    = (const float*)d_in[4];
    const float* W2    = (const float*)d_in[5];
    const float* b2    = (const float*)d_in[6];
    const float* Wl    = (const float*)d_in[7];
    const float* bl    = (const float*)d_in[8];
    const int* src = ei;
    const int* dst = ei + N_EDGES;

    cudaFuncSetAttribute(gemm_kernel<0>, cudaFuncAttributeMaxDynamicSharedMemorySize, GEMM_SMEM_BYTES);
    cudaFuncSetAttribute(gemm_kernel<1>, cudaFuncAttributeMaxDynamicSharedMemorySize, GEMM_SMEM_BYTES);

    const int ZB   = (N_NODES + 255) / 256;
    const int ZA   = (N_NODES * (HIDDEN / 4) + 255) / 256;
    const int EB   = (N_EDGES + 255) / 256;
    const int GEMB = (N_NODES + 63) / 64;
    const int SCB  = (N_EDGES * 32 + 255) / 256;
    const int FNB  = (N_NODES * 32 + 255) / 256;

    zero_small_kernel<<<ZB, 256>>>();
    zero_acc_kernel<<<ZA, 256>>>();
    deg_kernel<<<EB, 256>>>(dst);
    dinv_kernel<<<ZB, 256>>>();

    // Layer 1: p1 = (x @ W1) * dinv ; acc = scatter_add(p1)
    gemm_kernel<0><<<GEMB, 256, GEMM_SMEM_BYTES>>>(x, W1, nullptr);
    scatter_kernel<<<SCB, 256>>>(src, dst, 0);

    // Layer 2: in = relu(dinv*(acc+p1)+b1); p2 = (in @ W2) * dinv
    gemm_kernel<1><<<GEMB, 256, GEMM_SMEM_BYTES>>>(nullptr, W2, b1);
    zero_acc_kernel<<<ZA, 256>>>();
    scatter_kernel<<<SCB, 256>>>(src, dst, 1);

    // Final: per-node dot with Wl, segment mean per graph, + bl
    final_kernel<<<FNB, 256>>>(b2, Wl, batch);
    out_kernel<<<(N_GRAPHS + 255) / 256, 256>>>((float*)d_out, bl);
}

// round 4
// speedup vs baseline: 1.4738x; 1.4738x over previous
#include <cuda_runtime.h>
#include <cuda_bf16.h>
#include <cstdint>

#define N_NODES  50000
#define N_EDGES  800000
#define HIDDEN   128
#define N_GRAPHS 512

#define SCAN_BS  512
#define SCAN_NB  ((N_NODES + SCAN_BS - 1) / SCAN_BS)   // 98

// ---------------------------------------------------------------------------
// Static device scratch (~55 MB). All referenced ONLY from device code.
// ---------------------------------------------------------------------------
__device__ int   g_deg[N_NODES];
__device__ int   g_ptr[N_NODES];        // CSR row start (exclusive scan of deg)
__device__ int   g_fill[N_NODES];       // fill cursors
__device__ int   g_csr[N_EDGES];        // src ids grouped by dst
__device__ int   g_bsum[SCAN_NB];
__device__ int   g_boff[SCAN_NB];
__device__ float g_dinv[N_NODES];
__device__ float g_p[(size_t)N_NODES * HIDDEN];   // pre-scaled features (both layers)
__device__ float g_h[(size_t)N_NODES * HIDDEN];   // relu'd layer-1 output
__device__ float g_pool[N_GRAPHS];
__device__ float g_cnt[N_GRAPHS];

// ---------------------------------------------------------------------------
// Zero + degree + dinv + graph counts
// ---------------------------------------------------------------------------
__global__ void __launch_bounds__(256) zero_kernel() {
    int i = blockIdx.x * blockDim.x + threadIdx.x;
    if (i < N_NODES) g_deg[i] = 0;
    if (i < N_GRAPHS) { g_pool[i] = 0.0f; g_cnt[i] = 0.0f; }
}

__global__ void __launch_bounds__(256) deg_kernel(const int* __restrict__ dst) {
    int e = blockIdx.x * blockDim.x + threadIdx.x;
    if (e < N_EDGES) atomicAdd(&g_deg[dst[e]], 1);
}

__global__ void __launch_bounds__(256) dinv_kernel(const int* __restrict__ batch) {
    int i = blockIdx.x * blockDim.x + threadIdx.x;
    if (i < N_NODES) {
        g_dinv[i] = rsqrtf((float)g_deg[i] + 1.0f);
        atomicAdd(&g_cnt[batch[i]], 1.0f);
    }
}

// ---------------------------------------------------------------------------
// 3-kernel exclusive scan of g_deg -> g_ptr (and g_fill copy)
// ---------------------------------------------------------------------------
__global__ void __launch_bounds__(SCAN_BS) scan_k1() {
    __shared__ int s[SCAN_BS];
    int i = blockIdx.x * SCAN_BS + threadIdx.x;
    s[threadIdx.x] = (i < N_NODES) ? g_deg[i] : 0;
    __syncthreads();
    for (int off = SCAN_BS / 2; off > 0; off >>= 1) {
        if (threadIdx.x < off) s[threadIdx.x] += s[threadIdx.x + off];
        __syncthreads();
    }
    if (threadIdx.x == 0) g_bsum[blockIdx.x] = s[0];
}

__global__ void __launch_bounds__(32) scan_k2() {
    if (threadIdx.x == 0 && blockIdx.x == 0) {
        int run = 0;
        for (int b = 0; b < SCAN_NB; b++) { g_boff[b] = run; run += g_bsum[b]; }
    }
}

__global__ void __launch_bounds__(SCAN_BS) scan_k3() {
    __shared__ int s[SCAN_BS];
    int i = blockIdx.x * SCAN_BS + threadIdx.x;
    int d = (i < N_NODES) ? g_deg[i] : 0;
    s[threadIdx.x] = d;
    __syncthreads();
    for (int off = 1; off < SCAN_BS; off <<= 1) {
        int v = (threadIdx.x >= off) ? s[threadIdx.x - off] : 0;
        __syncthreads();
        s[threadIdx.x] += v;
        __syncthreads();
    }
    if (i < N_NODES) {
        int p = g_boff[blockIdx.x] + s[threadIdx.x] - d;  // exclusive
        g_ptr[i] = p;
        g_fill[i] = p;
    }
}

__global__ void __launch_bounds__(256) fill_kernel(const int* __restrict__ src,
                                                   const int* __restrict__ dst) {
    int e = blockIdx.x * blockDim.x + threadIdx.x;
    if (e < N_EDGES) {
        int pos = atomicAdd(&g_fill[dst[e]], 1);
        g_csr[pos] = src[e];
    }
}

// ---------------------------------------------------------------------------
// GEMM: g_p[row] = (in[row] @ W) * dinv[row].
//   MODE 0: in = X (kernel argument)
//   MODE 1: in = g_h (device global)
// 256 thr, 64-row tiles, warp handles 8 rows, lane l owns cols [4l, 4l+4).
// ---------------------------------------------------------------------------
#define GEMM_SMEM_BYTES ((16384 + 8192) * 4)

template <int MODE>
__global__ void __launch_bounds__(256) gemm_kernel(const float* __restrict__ X,
                                                   const float* __restrict__ W) {
    extern __shared__ float smem[];
    float* Ws = smem;            // 128*128
    float* Xs = smem + 16384;    // 64*128

    const int tid = threadIdx.x;
    const float* in = (MODE == 0) ? X : g_h;

    const float4* W4 = reinterpret_cast<const float4*>(W);
    float4* Ws4 = reinterpret_cast<float4*>(Ws);
    #pragma unroll
    for (int i = tid; i < 4096; i += 256) Ws4[i] = W4[i];

    const int row0 = blockIdx.x * 64;
    for (int i = tid; i < 2048; i += 256) {
        int r = i >> 5, seg = i & 31;
        int row = row0 + r;
        float4 v = make_float4(0.f, 0.f, 0.f, 0.f);
        if (row < N_NODES)
            v = reinterpret_cast<const float4*>(in + (size_t)row * HIDDEN)[seg];
        reinterpret_cast<float4*>(Xs + r * HIDDEN)[seg] = v;
    }
    __syncthreads();

    const int w = tid >> 5, l = tid & 31;
    const int rbase = w * 8;

    float4 acc[8];
    #pragma unroll
    for (int r = 0; r < 8; r++) acc[r] = make_float4(0.f, 0.f, 0.f, 0.f);

    const float4* Ws4c = reinterpret_cast<const float4*>(Ws);
    #pragma unroll 4
    for (int k4 = 0; k4 < 32; k4++) {
        float4 w0 = Ws4c[(4 * k4 + 0) * 32 + l];
        float4 w1 = Ws4c[(4 * k4 + 1) * 32 + l];
        float4 w2 = Ws4c[(4 * k4 + 2) * 32 + l];
        float4 w3 = Ws4c[(4 * k4 + 3) * 32 + l];
        #pragma unroll
        for (int r = 0; r < 8; r++) {
            float4 xq = reinterpret_cast<const float4*>(Xs + (rbase + r) * HIDDEN)[k4];
            acc[r].x += xq.x * w0.x + xq.y * w1.x + xq.z * w2.x + xq.w * w3.x;
            acc[r].y += xq.x * w0.y + xq.y * w1.y + xq.z * w2.y + xq.w * w3.y;
            acc[r].z += xq.x * w0.z + xq.y * w1.z + xq.z * w2.z + xq.w * w3.z;
            acc[r].w += xq.x * w0.w + xq.y * w1.w + xq.z * w2.w + xq.w * w3.w;
        }
    }

    #pragma unroll
    for (int r = 0; r < 8; r++) {
        int row = row0 + rbase + r;
        if (row < N_NODES) {
            float di = g_dinv[row];
            float4 o = make_float4(acc[r].x * di, acc[r].y * di,
                                   acc[r].z * di, acc[r].w * di);
            reinterpret_cast<float4*>(g_p + (size_t)row * HIDDEN)[l] = o;
        }
    }
}

// ---------------------------------------------------------------------------
// CSR aggregation, one warp per node, reads g_p directly:
//   acc = p[n] + sum_{src in in(n)} p[src];  h = relu(dinv[n]*acc + b)
// LAYER 1: write h to g_h.
// LAYER 2: s = dot(h, Wl); atomicAdd into per-graph pool.
// ---------------------------------------------------------------------------
template <int LAYER>
__global__ void __launch_bounds__(256) agg_kernel(const float* __restrict__ bias,
                                                  const float* __restrict__ Wl,
                                                  const int* __restrict__ batch) {
    int t = blockIdx.x * blockDim.x + threadIdx.x;
    int n = t >> 5;
    int l = t & 31;
    if (n >= N_NODES) return;

    const float4* P4 = reinterpret_cast<const float4*>(g_p);
    float4 acc = __ldg(&P4[(size_t)n * 32 + l]);   // self term

    int base = g_ptr[n];
    int deg  = g_deg[n];
    int i = 0;
    for (; i + 4 <= deg; i += 4) {
        int s0 = g_csr[base + i + 0];
        int s1 = g_csr[base + i + 1];
        int s2 = g_csr[base + i + 2];
        int s3 = g_csr[base + i + 3];
        float4 v0 = __ldg(&P4[(size_t)s0 * 32 + l]);
        float4 v1 = __ldg(&P4[(size_t)s1 * 32 + l]);
        float4 v2 = __ldg(&P4[(size_t)s2 * 32 + l]);
        float4 v3 = __ldg(&P4[(size_t)s3 * 32 + l]);
        acc.x += (v0.x + v1.x) + (v2.x + v3.x);
        acc.y += (v0.y + v1.y) + (v2.y + v3.y);
        acc.z += (v0.z + v1.z) + (v2.z + v3.z);
        acc.w += (v0.w + v1.w) + (v2.w + v3.w);
    }
    for (; i < deg; i++) {
        int s = g_csr[base + i];
        float4 v = __ldg(&P4[(size_t)s * 32 + l]);
        acc.x += v.x; acc.y += v.y; acc.z += v.z; acc.w += v.w;
    }

    float di = g_dinv[n];
    float4 b = __ldg(reinterpret_cast<const float4*>(bias) + l);
    float h0 = fmaxf(di * acc.x + b.x, 0.f);
    float h1 = fmaxf(di * acc.y + b.y, 0.f);
    float h2 = fmaxf(di * acc.z + b.z, 0.f);
    float h3 = fmaxf(di * acc.w + b.w, 0.f);

    if (LAYER == 1) {
        reinterpret_cast<float4*>(g_h)[(size_t)n * 32 + l] =
            make_float4(h0, h1, h2, h3);
    } else {
        float4 wl = __ldg(reinterpret_cast<const float4*>(Wl) + l);
        float s = h0 * wl.x + h1 * wl.y + h2 * wl.z + h3 * wl.w;
        #pragma unroll
        for (int off = 16; off; off >>= 1) s += __shfl_xor_sync(0xffffffffu, s, off);
        if (l == 0) atomicAdd(&g_pool[__ldg(&batch[n])], s);
    }
}

__global__ void __launch_bounds__(256) out_kernel(float* __restrict__ out,
                                                  const float* __restrict__ bl) {
    int g = blockIdx.x * blockDim.x + threadIdx.x;
    if (g < N_GRAPHS) out[g] = g_pool[g] / fmaxf(g_cnt[g], 1.0f) + bl[0];
}

// ---------------------------------------------------------------------------
// Launch — no __device__ symbol addresses ever taken on the host.
// ---------------------------------------------------------------------------
extern "C" void kernel_launch(void* const* d_in, const int* in_sizes, int n_in,
                              void* d_out, int out_size) {
    const float* x     = (const float*)d_in[0];
    const int*   ei    = (const int*)  d_in[1];
    const int*   batch = (const int*)  d_in[2];
    const float* W1    = (const float*)d_in[3];
    const float* b1    = (const float*)d_in[4];
    const float* W2    = (const float*)d_in[5];
    const float* b2    = (const float*)d_in[6];
    const float* Wl    = (const float*)d_in[7];
    const float* bl    = (const float*)d_in[8];
    const int* src = ei;
    const int* dst = ei + N_EDGES;

    cudaFuncSetAttribute(gemm_kernel<0>, cudaFuncAttributeMaxDynamicSharedMemorySize,
                         GEMM_SMEM_BYTES);
    cudaFuncSetAttribute(gemm_kernel<1>, cudaFuncAttributeMaxDynamicSharedMemorySize,
                         GEMM_SMEM_BYTES);

    const int ZB   = (N_NODES + 255) / 256;
    const int EB   = (N_EDGES + 255) / 256;
    const int GEMB = (N_NODES + 63) / 64;
    const int AGB  = (N_NODES * 32 + 255) / 256;

    // --- graph structure (shared by both layers) ---
    zero_kernel<<<ZB, 256>>>();
    deg_kernel<<<EB, 256>>>(dst);
    dinv_kernel<<<ZB, 256>>>(batch);
    scan_k1<<<SCAN_NB, SCAN_BS>>>();
    scan_k2<<<1, 32>>>();
    scan_k3<<<SCAN_NB, SCAN_BS>>>();
    fill_kernel<<<EB, 256>>>(src, dst);

    // --- layer 1: p = (x @ W1) * dinv ; h = relu(dinv*(gather(p)+p)+b1) ---
    gemm_kernel<0><<<GEMB, 256, GEMM_SMEM_BYTES>>>(x, W1);
    agg_kernel<1><<<AGB, 256>>>(b1, nullptr, nullptr);

    // --- layer 2: p = (h @ W2) * dinv ; fused epilogue + Wl dot + pooling ---
    gemm_kernel<1><<<GEMB, 256, GEMM_SMEM_BYTES>>>(nullptr, W2);
    agg_kernel<2><<<AGB, 256>>>(b2, Wl, batch);

    out_kernel<<<(N_GRAPHS + 255) / 256, 256>>>((float*)d_out, bl);
}

// round 5
// speedup vs baseline: 1.6359x; 1.1100x over previous
#include <cuda_runtime.h>
#include <cuda_fp16.h>
#include <cuda_bf16.h>
#include <cstdint>

#define N_NODES  50000
#define N_EDGES  800000
#define HIDDEN   128
#define N_GRAPHS 512

#define SCAN_BS  512
#define SCAN_NB  ((N_NODES + SCAN_BS - 1) / SCAN_BS)   // 98

// ---------------------------------------------------------------------------
// Static device scratch (~42 MB). Referenced ONLY from device code.
// ---------------------------------------------------------------------------
__device__ int    g_deg[N_NODES];
__device__ int    g_ptr[N_NODES];
__device__ int    g_fill[N_NODES];
__device__ int    g_csr[N_EDGES];
__device__ int    g_bsum[SCAN_NB];
__device__ int    g_boff[SCAN_NB];
__device__ float  g_dinv[N_NODES];
__device__ __half g_ph[(size_t)N_NODES * HIDDEN];  // fp16 pre-scaled features
__device__ float  g_h[(size_t)N_NODES * HIDDEN];   // fp32 relu'd layer-1 output
__device__ float  g_pool[N_GRAPHS];
__device__ float  g_cnt[N_GRAPHS];

// ---------------------------------------------------------------------------
__global__ void __launch_bounds__(256) zero_kernel() {
    int i = blockIdx.x * blockDim.x + threadIdx.x;
    if (i < N_NODES) g_deg[i] = 0;
    if (i < N_GRAPHS) { g_pool[i] = 0.0f; g_cnt[i] = 0.0f; }
}

__global__ void __launch_bounds__(256) deg_kernel(const int* __restrict__ dst) {
    int e = blockIdx.x * blockDim.x + threadIdx.x;
    if (e < N_EDGES) atomicAdd(&g_deg[dst[e]], 1);
}

// scan stage 1 + dinv + graph counts fused (all read g_deg / per-node data)
__global__ void __launch_bounds__(SCAN_BS) scan_k1(const int* __restrict__ batch) {
    __shared__ int s[SCAN_BS];
    int i = blockIdx.x * SCAN_BS + threadIdx.x;
    int d = (i < N_NODES) ? g_deg[i] : 0;
    if (i < N_NODES) {
        g_dinv[i] = rsqrtf((float)d + 1.0f);
        atomicAdd(&g_cnt[batch[i]], 1.0f);
    }
    s[threadIdx.x] = d;
    __syncthreads();
    for (int off = SCAN_BS / 2; off > 0; off >>= 1) {
        if (threadIdx.x < off) s[threadIdx.x] += s[threadIdx.x + off];
        __syncthreads();
    }
    if (threadIdx.x == 0) g_bsum[blockIdx.x] = s[0];
}

__global__ void __launch_bounds__(32) scan_k2() {
    if (threadIdx.x == 0 && blockIdx.x == 0) {
        int run = 0;
        for (int b = 0; b < SCAN_NB; b++) { g_boff[b] = run; run += g_bsum[b]; }
    }
}

__global__ void __launch_bounds__(SCAN_BS) scan_k3() {
    __shared__ int s[SCAN_BS];
    int i = blockIdx.x * SCAN_BS + threadIdx.x;
    int d = (i < N_NODES) ? g_deg[i] : 0;
    s[threadIdx.x] = d;
    __syncthreads();
    for (int off = 1; off < SCAN_BS; off <<= 1) {
        int v = (threadIdx.x >= off) ? s[threadIdx.x - off] : 0;
        __syncthreads();
        s[threadIdx.x] += v;
        __syncthreads();
    }
    if (i < N_NODES) {
        int p = g_boff[blockIdx.x] + s[threadIdx.x] - d;  // exclusive
        g_ptr[i] = p;
        g_fill[i] = p;
    }
}

__global__ void __launch_bounds__(256) fill_kernel(const int* __restrict__ src,
                                                   const int* __restrict__ dst) {
    int e = blockIdx.x * blockDim.x + threadIdx.x;
    if (e < N_EDGES) {
        int pos = atomicAdd(&g_fill[dst[e]], 1);
        g_csr[pos] = src[e];
    }
}

// ---------------------------------------------------------------------------
// GEMM: g_ph[row] = half( (in[row] @ W) * dinv[row] )
//   MODE 0: in = X (kernel argument)    MODE 1: in = g_h (device global)
// ---------------------------------------------------------------------------
#define GEMM_SMEM_BYTES ((16384 + 8192) * 4)

template <int MODE>
__global__ void __launch_bounds__(256) gemm_kernel(const float* __restrict__ X,
                                                   const float* __restrict__ W) {
    extern __shared__ float smem[];
    float* Ws = smem;            // 128*128
    float* Xs = smem + 16384;    // 64*128

    const int tid = threadIdx.x;
    const float* in = (MODE == 0) ? X : g_h;

    const float4* W4 = reinterpret_cast<const float4*>(W);
    float4* Ws4 = reinterpret_cast<float4*>(Ws);
    #pragma unroll
    for (int i = tid; i < 4096; i += 256) Ws4[i] = W4[i];

    const int row0 = blockIdx.x * 64;
    for (int i = tid; i < 2048; i += 256) {
        int r = i >> 5, seg = i & 31;
        int row = row0 + r;
        float4 v = make_float4(0.f, 0.f, 0.f, 0.f);
        if (row < N_NODES)
            v = reinterpret_cast<const float4*>(in + (size_t)row * HIDDEN)[seg];
        reinterpret_cast<float4*>(Xs + r * HIDDEN)[seg] = v;
    }
    __syncthreads();

    const int w = tid >> 5, l = tid & 31;
    const int rbase = w * 8;

    float4 acc[8];
    #pragma unroll
    for (int r = 0; r < 8; r++) acc[r] = make_float4(0.f, 0.f, 0.f, 0.f);

    const float4* Ws4c = reinterpret_cast<const float4*>(Ws);
    #pragma unroll 4
    for (int k4 = 0; k4 < 32; k4++) {
        float4 w0 = Ws4c[(4 * k4 + 0) * 32 + l];
        float4 w1 = Ws4c[(4 * k4 + 1) * 32 + l];
        float4 w2 = Ws4c[(4 * k4 + 2) * 32 + l];
        float4 w3 = Ws4c[(4 * k4 + 3) * 32 + l];
        #pragma unroll
        for (int r = 0; r < 8; r++) {
            float4 xq = reinterpret_cast<const float4*>(Xs + (rbase + r) * HIDDEN)[k4];
            acc[r].x += xq.x * w0.x + xq.y * w1.x + xq.z * w2.x + xq.w * w3.x;
            acc[r].y += xq.x * w0.y + xq.y * w1.y + xq.z * w2.y + xq.w * w3.y;
            acc[r].z += xq.x * w0.z + xq.y * w1.z + xq.z * w2.z + xq.w * w3.z;
            acc[r].w += xq.x * w0.w + xq.y * w1.w + xq.z * w2.w + xq.w * w3.w;
        }
    }

    #pragma unroll
    for (int r = 0; r < 8; r++) {
        int row = row0 + rbase + r;
        if (row < N_NODES) {
            float di = g_dinv[row];
            __half2 h01 = __floats2half2_rn(acc[r].x * di, acc[r].y * di);
            __half2 h23 = __floats2half2_rn(acc[r].z * di, acc[r].w * di);
            uint2 pk;
            pk.x = *reinterpret_cast<uint32_t*>(&h01);
            pk.y = *reinterpret_cast<uint32_t*>(&h23);
            reinterpret_cast<uint2*>(g_ph + (size_t)row * HIDDEN)[l] = pk;
        }
    }
}

// ---------------------------------------------------------------------------
// CSR aggregation (fp16 gather, fp32 accumulate), one warp per node.
// ---------------------------------------------------------------------------
__device__ __forceinline__ void acc_h4(float4& acc, uint2 raw) {
    __half2 a = *reinterpret_cast<__half2*>(&raw.x);
    __half2 b = *reinterpret_cast<__half2*>(&raw.y);
    float2 f0 = __half22float2(a);
    float2 f1 = __half22float2(b);
    acc.x += f0.x; acc.y += f0.y; acc.z += f1.x; acc.w += f1.y;
}

template <int LAYER>
__global__ void __launch_bounds__(256) agg_kernel(const float* __restrict__ bias,
                                                  const float* __restrict__ Wl,
                                                  const int* __restrict__ batch) {
    int t = blockIdx.x * blockDim.x + threadIdx.x;
    int n = t >> 5;
    int l = t & 31;
    if (n >= N_NODES) return;

    const uint2* P2 = reinterpret_cast<const uint2*>(g_ph);
    float4 acc = make_float4(0.f, 0.f, 0.f, 0.f);
    acc_h4(acc, __ldg(&P2[(size_t)n * 32 + l]));   // self term

    int base = g_ptr[n];
    int deg  = g_deg[n];
    int i = 0;
    for (; i + 4 <= deg; i += 4) {
        int s0 = g_csr[base + i + 0];
        int s1 = g_csr[base + i + 1];
        int s2 = g_csr[base + i + 2];
        int s3 = g_csr[base + i + 3];
        uint2 v0 = __ldg(&P2[(size_t)s0 * 32 + l]);
        uint2 v1 = __ldg(&P2[(size_t)s1 * 32 + l]);
        uint2 v2 = __ldg(&P2[(size_t)s2 * 32 + l]);
        uint2 v3 = __ldg(&P2[(size_t)s3 * 32 + l]);
        acc_h4(acc, v0); acc_h4(acc, v1); acc_h4(acc, v2); acc_h4(acc, v3);
    }
    for (; i < deg; i++) {
        int s = g_csr[base + i];
        acc_h4(acc, __ldg(&P2[(size_t)s * 32 + l]));
    }

    float di = g_dinv[n];
    float4 b = __ldg(reinterpret_cast<const float4*>(bias) + l);
    float h0 = fmaxf(di * acc.x + b.x, 0.f);
    float h1 = fmaxf(di * acc.y + b.y, 0.f);
    float h2 = fmaxf(di * acc.z + b.z, 0.f);
    float h3 = fmaxf(di * acc.w + b.w, 0.f);

    if (LAYER == 1) {
        reinterpret_cast<float4*>(g_h)[(size_t)n * 32 + l] =
            make_float4(h0, h1, h2, h3);
    } else {
        float4 wl = __ldg(reinterpret_cast<const float4*>(Wl) + l);
        float s = h0 * wl.x + h1 * wl.y + h2 * wl.z + h3 * wl.w;
        #pragma unroll
        for (int off = 16; off; off >>= 1) s += __shfl_xor_sync(0xffffffffu, s, off);
        if (l == 0) atomicAdd(&g_pool[__ldg(&batch[n])], s);
    }
}

__global__ void __launch_bounds__(256) out_kernel(float* __restrict__ out,
                                                  const float* __restrict__ bl) {
    int g = blockIdx.x * blockDim.x + threadIdx.x;
    if (g < N_GRAPHS) out[g] = g_pool[g] / fmaxf(g_cnt[g], 1.0f) + bl[0];
}

// ---------------------------------------------------------------------------
extern "C" void kernel_launch(void* const* d_in, const int* in_sizes, int n_in,
                              void* d_out, int out_size) {
    const float* x     = (const float*)d_in[0];
    const int*   ei    = (const int*)  d_in[1];
    const int*   batch = (const int*)  d_in[2];
    const float* W1    = (const float*)d_in[3];
    const float* b1    = (const float*)d_in[4];
    const float* W2    = (const float*)d_in[5];
    const float* b2    = (const float*)d_in[6];
    const float* Wl    = (const float*)d_in[7];
    const float* bl    = (const float*)d_in[8];
    const int* src = ei;
    const int* dst = ei + N_EDGES;

    cudaFuncSetAttribute(gemm_kernel<0>, cudaFuncAttributeMaxDynamicSharedMemorySize,
                         GEMM_SMEM_BYTES);
    cudaFuncSetAttribute(gemm_kernel<1>, cudaFuncAttributeMaxDynamicSharedMemorySize,
                         GEMM_SMEM_BYTES);

    const int ZB   = (N_NODES + 255) / 256;
    const int EB   = (N_EDGES + 255) / 256;
    const int GEMB = (N_NODES + 63) / 64;
    const int AGB  = (N_NODES * 32 + 255) / 256;

    // --- graph structure (shared by both layers) ---
    zero_kernel<<<ZB, 256>>>();
    deg_kernel<<<EB, 256>>>(dst);
    scan_k1<<<SCAN_NB, SCAN_BS>>>(batch);    // + dinv + graph counts
    scan_k2<<<1, 32>>>();
    scan_k3<<<SCAN_NB, SCAN_BS>>>();
    fill_kernel<<<EB, 256>>>(src, dst);

    // --- layer 1 ---
    gemm_kernel<0><<<GEMB, 256, GEMM_SMEM_BYTES>>>(x, W1);
    agg_kernel<1><<<AGB, 256>>>(b1, nullptr, nullptr);

    // --- layer 2 (epilogue + Wl dot + pooling fused) ---
    gemm_kernel<1><<<GEMB, 256, GEMM_SMEM_BYTES>>>(nullptr, W2);
    agg_kernel<2><<<AGB, 256>>>(b2, Wl, batch);

    out_kernel<<<(N_GRAPHS + 255) / 256, 256>>>((float*)d_out, bl);
}

// round 7
// speedup vs baseline: 2.7259x; 1.6662x over previous
#include <cuda_runtime.h>
#include <cuda_fp16.h>
#include <cuda_bf16.h>
#include <cstdint>

#define N_NODES  50000
#define N_EDGES  800000
#define HIDDEN   128
#define N_GRAPHS 512

#define SCAN_BS  512
#define SCAN_NB  ((N_NODES + SCAN_BS - 1) / SCAN_BS)   // 98

// ---------------------------------------------------------------------------
// Static device scratch (~30 MB). Referenced ONLY from device code.
// ---------------------------------------------------------------------------
__device__ int    g_deg[N_NODES];
__device__ int    g_ptr[N_NODES];
__device__ int    g_fill[N_NODES];
__device__ int    g_csr[N_EDGES];
__device__ int    g_bsum[SCAN_NB];
__device__ int    g_boff[SCAN_NB];
__device__ float  g_dinv[N_NODES];
__device__ __half g_ph[(size_t)N_NODES * HIDDEN];  // fp16 pre-scaled features
__device__ __half g_hh[(size_t)N_NODES * HIDDEN];  // fp16 relu'd layer-1 output
__device__ float  g_pool[N_GRAPHS];
__device__ float  g_cnt[N_GRAPHS];

// ---------------------------------------------------------------------------
__global__ void __launch_bounds__(256) zero_kernel() {
    int i = blockIdx.x * blockDim.x + threadIdx.x;
    if (i < N_NODES) g_deg[i] = 0;
    if (i < N_GRAPHS) { g_pool[i] = 0.0f; g_cnt[i] = 0.0f; }
}

__global__ void __launch_bounds__(256) deg_kernel(const int* __restrict__ dst) {
    int e = blockIdx.x * blockDim.x + threadIdx.x;
    if (e < N_EDGES) atomicAdd(&g_deg[dst[e]], 1);
}

// scan stage 1 + dinv + graph counts fused
__global__ void __launch_bounds__(SCAN_BS) scan_k1(const int* __restrict__ batch) {
    __shared__ int s[SCAN_BS];
    int i = blockIdx.x * SCAN_BS + threadIdx.x;
    int d = (i < N_NODES) ? g_deg[i] : 0;
    if (i < N_NODES) {
        g_dinv[i] = rsqrtf((float)d + 1.0f);
        atomicAdd(&g_cnt[batch[i]], 1.0f);
    }
    s[threadIdx.x] = d;
    __syncthreads();
    for (int off = SCAN_BS / 2; off > 0; off >>= 1) {
        if (threadIdx.x < off) s[threadIdx.x] += s[threadIdx.x + off];
        __syncthreads();
    }
    if (threadIdx.x == 0) g_bsum[blockIdx.x] = s[0];
}

// parallel scan of 98 block sums (shuffle 2-level)
__global__ void __launch_bounds__(128) scan_k2() {
    __shared__ int wsum[4];
    int tid = threadIdx.x;
    int v = (tid < SCAN_NB) ? g_bsum[tid] : 0;
    int lane = tid & 31, w = tid >> 5;
    int inc = v;
    #pragma unroll
    for (int off = 1; off < 32; off <<= 1) {
        int t = __shfl_up_sync(0xffffffffu, inc, off);
        if (lane >= off) inc += t;
    }
    if (lane == 31) wsum[w] = inc;
    __syncthreads();
    if (tid == 0) {
        int r = 0;
        #pragma unroll
        for (int i = 0; i < 4; i++) { int t = wsum[i]; wsum[i] = r; r += t; }
    }
    __syncthreads();
    if (tid < SCAN_NB) g_boff[tid] = inc - v + wsum[w];
}

__global__ void __launch_bounds__(SCAN_BS) scan_k3() {
    __shared__ int s[SCAN_BS];
    int i = blockIdx.x * SCAN_BS + threadIdx.x;
    int d = (i < N_NODES) ? g_deg[i] : 0;
    s[threadIdx.x] = d;
    __syncthreads();
    for (int off = 1; off < SCAN_BS; off <<= 1) {
        int v = (threadIdx.x >= off) ? s[threadIdx.x - off] : 0;
        __syncthreads();
        s[threadIdx.x] += v;
        __syncthreads();
    }
    if (i < N_NODES) {
        int p = g_boff[blockIdx.x] + s[threadIdx.x] - d;  // exclusive
        g_ptr[i] = p;
        g_fill[i] = p;
    }
}

__global__ void __launch_bounds__(256) fill_kernel(const int* __restrict__ src,
                                                   const int* __restrict__ dst) {
    int e = blockIdx.x * blockDim.x + threadIdx.x;
    if (e < N_EDGES) {
        int pos = atomicAdd(&g_fill[dst[e]], 1);
        g_csr[pos] = src[e];
    }
}

// ---------------------------------------------------------------------------
// Tensor-core GEMM: g_ph[row] = half( (in[row] @ W) * dinv[row] )
//   MODE 0: in = X fp32 (arg)     MODE 1: in = g_hh fp16 (device global)
// Block: 256 thr (8 warps), tile 128 rows x 128 cols, K=128 fully smem-resident.
// Warp w: rows 32*(w>>1), cols 64*(w&1): 2 m-tiles x 8 n-tiles of m16n8k16.
// Smem stride 136 halves (272 B): rows land 16 B apart mod 128 -> ldmatrix
// conflict-free in every 8-lane phase (both trans and non-trans).
// ---------------------------------------------------------------------------
#define AS_STRIDE 136
#define GEMM_TC_SMEM (2 * 128 * AS_STRIDE * 2)   // 69632 B

__device__ __forceinline__ uint32_t smem_u32(const void* p) {
    return (uint32_t)__cvta_generic_to_shared(p);
}
__device__ __forceinline__ void ldsm_x4(uint32_t& r0, uint32_t& r1,
                                        uint32_t& r2, uint32_t& r3, uint32_t a) {
    asm volatile("ldmatrix.sync.aligned.m8n8.x4.shared.b16 {%0,%1,%2,%3},[%4];"
                 : "=r"(r0), "=r"(r1), "=r"(r2), "=r"(r3) : "r"(a));
}
__device__ __forceinline__ void ldsm_x2t(uint32_t& r0, uint32_t& r1, uint32_t a) {
    asm volatile("ldmatrix.sync.aligned.m8n8.x2.trans.shared.b16 {%0,%1},[%2];"
                 : "=r"(r0), "=r"(r1) : "r"(a));
}
__device__ __forceinline__ void mma16816(float* c, const uint32_t* a, const uint32_t* b) {
    asm volatile("mma.sync.aligned.m16n8k16.row.col.f32.f16.f16.f32 "
                 "{%0,%1,%2,%3},{%4,%5,%6,%7},{%8,%9},{%0,%1,%2,%3};"
                 : "+f"(c[0]), "+f"(c[1]), "+f"(c[2]), "+f"(c[3])
                 : "r"(a[0]), "r"(a[1]), "r"(a[2]), "r"(a[3]), "r"(b[0]), "r"(b[1]));
}

template <int MODE>
__global__ void __launch_bounds__(256) gemm_tc(const float* __restrict__ X,
                                               const float* __restrict__ W) {
    extern __shared__ __half smem[];
    __half* As = smem;                         // 128 x 136
    __half* Ws = smem + 128 * AS_STRIDE;       // 128 x 136 (row = k, col = n)

    const int tid = threadIdx.x;
    const int row0 = blockIdx.x * 128;

    // Stage W (fp32 -> fp16), row-major [k][n]: 4096 float4 = 128 rows x 32 segs
    const float4* W4 = reinterpret_cast<const float4*>(W);
    for (int j = tid; j < 4096; j += 256) {
        int r = j >> 5, s = j & 31;
        float4 v = W4[j];
        __half2 h0 = __floats2half2_rn(v.x, v.y);
        __half2 h1 = __floats2half2_rn(v.z, v.w);
        uint2 pk;
        pk.x = *reinterpret_cast<uint32_t*>(&h0);
        pk.y = *reinterpret_cast<uint32_t*>(&h1);
        *reinterpret_cast<uint2*>(Ws + r * AS_STRIDE + s * 4) = pk;
    }
    // Stage A tile: 128 rows
    if (MODE == 0) {
        for (int j = tid; j < 4096; j += 256) {     // FIXED: 128 rows x 32 segs
            int r = j >> 5, s = j & 31;
            int row = row0 + r;
            float4 v = make_float4(0.f, 0.f, 0.f, 0.f);
            if (row < N_NODES)
                v = reinterpret_cast<const float4*>(X + (size_t)row * HIDDEN)[s];
            __half2 h0 = __floats2half2_rn(v.x, v.y);
            __half2 h1 = __floats2half2_rn(v.z, v.w);
            uint2 pk;
            pk.x = *reinterpret_cast<uint32_t*>(&h0);
            pk.y = *reinterpret_cast<uint32_t*>(&h1);
            *reinterpret_cast<uint2*>(As + r * AS_STRIDE + s * 4) = pk;
        }
    } else {
        for (int j = tid; j < 2048; j += 256) {     // 128 rows x 16 uint4 segs
            int r = j >> 4, s = j & 15;
            int row = row0 + r;
            uint4 v = make_uint4(0u, 0u, 0u, 0u);
            if (row < N_NODES)
                v = reinterpret_cast<const uint4*>(g_hh)[(size_t)row * 16 + s];
            *reinterpret_cast<uint4*>(As + r * AS_STRIDE + s * 8) = v;
        }
    }
    __syncthreads();

    const int w = tid >> 5, lane = tid & 31;
    const int m0 = (w >> 1) * 32;
    const int n0g = (w & 1) * 64;

    float c[2][8][4];
    #pragma unroll
    for (int mt = 0; mt < 2; mt++)
        #pragma unroll
        for (int nt = 0; nt < 8; nt++)
            #pragma unroll
            for (int q = 0; q < 4; q++) c[mt][nt][q] = 0.f;

    const int arow = lane & 15, acol = (lane >> 4) * 8;
    const int brow = lane & 15;

    #pragma unroll
    for (int kc = 0; kc < 8; kc++) {
        const int k0 = kc * 16;
        uint32_t a[2][4];
        #pragma unroll
        for (int mt = 0; mt < 2; mt++) {
            uint32_t addr = smem_u32(As + (m0 + mt * 16 + arow) * AS_STRIDE + k0 + acol);
            ldsm_x4(a[mt][0], a[mt][1], a[mt][2], a[mt][3], addr);
        }
        #pragma unroll
        for (int nt = 0; nt < 8; nt++) {
            uint32_t b[2];
            uint32_t baddr = smem_u32(Ws + (k0 + brow) * AS_STRIDE + n0g + nt * 8);
            ldsm_x2t(b[0], b[1], baddr);
            mma16816(c[0][nt], a[0], b);
            mma16816(c[1][nt], a[1], b);
        }
    }

    // Epilogue: scale by dinv, convert to fp16, store g_ph
    #pragma unroll
    for (int mt = 0; mt < 2; mt++) {
        int r0g = row0 + m0 + mt * 16 + (lane >> 2);
        int r1g = r0g + 8;
        float d0 = (r0g < N_NODES) ? g_dinv[r0g] : 0.f;
        float d1 = (r1g < N_NODES) ? g_dinv[r1g] : 0.f;
        #pragma unroll
        for (int nt = 0; nt < 8; nt++) {
            int col = n0g + nt * 8 + 2 * (lane & 3);
            if (r0g < N_NODES) {
                __half2 h = __floats2half2_rn(c[mt][nt][0] * d0, c[mt][nt][1] * d0);
                *reinterpret_cast<__half2*>(g_ph + (size_t)r0g * HIDDEN + col) = h;
            }
            if (r1g < N_NODES) {
                __half2 h = __floats2half2_rn(c[mt][nt][2] * d1, c[mt][nt][3] * d1);
                *reinterpret_cast<__half2*>(g_ph + (size_t)r1g * HIDDEN + col) = h;
            }
        }
    }
}

// ---------------------------------------------------------------------------
// CSR aggregation (fp16 gather, fp32 accumulate), one warp per node.
// LAYER 1: h -> g_hh (fp16).  LAYER 2: dot(h, Wl) -> per-graph pool.
// ---------------------------------------------------------------------------
__device__ __forceinline__ void acc_h4(float4& acc, uint2 raw) {
    __half2 a = *reinterpret_cast<__half2*>(&raw.x);
    __half2 b = *reinterpret_cast<__half2*>(&raw.y);
    float2 f0 = __half22float2(a);
    float2 f1 = __half22float2(b);
    acc.x += f0.x; acc.y += f0.y; acc.z += f1.x; acc.w += f1.y;
}

template <int LAYER>
__global__ void __launch_bounds__(256) agg_kernel(const float* __restrict__ bias,
                                                  const float* __restrict__ Wl,
                                                  const int* __restrict__ batch) {
    int t = blockIdx.x * blockDim.x + threadIdx.x;
    int n = t >> 5;
    int l = t & 31;
    if (n >= N_NODES) return;

    const uint2* P2 = reinterpret_cast<const uint2*>(g_ph);
    float4 acc = make_float4(0.f, 0.f, 0.f, 0.f);
    acc_h4(acc, __ldg(&P2[(size_t)n * 32 + l]));   // self term

    int base = g_ptr[n];
    int deg  = g_deg[n];
    int i = 0;
    for (; i + 4 <= deg; i += 4) {
        int s0 = g_csr[base + i + 0];
        int s1 = g_csr[base + i + 1];
        int s2 = g_csr[base + i + 2];
        int s3 = g_csr[base + i + 3];
        uint2 v0 = __ldg(&P2[(size_t)s0 * 32 + l]);
        uint2 v1 = __ldg(&P2[(size_t)s1 * 32 + l]);
        uint2 v2 = __ldg(&P2[(size_t)s2 * 32 + l]);
        uint2 v3 = __ldg(&P2[(size_t)s3 * 32 + l]);
        acc_h4(acc, v0); acc_h4(acc, v1); acc_h4(acc, v2); acc_h4(acc, v3);
    }
    for (; i < deg; i++) {
        int s = g_csr[base + i];
        acc_h4(acc, __ldg(&P2[(size_t)s * 32 + l]));
    }

    float di = g_dinv[n];
    float4 b = __ldg(reinterpret_cast<const float4*>(bias) + l);
    float h0 = fmaxf(di * acc.x + b.x, 0.f);
    float h1 = fmaxf(di * acc.y + b.y, 0.f);
    float h2 = fmaxf(di * acc.z + b.z, 0.f);
    float h3 = fmaxf(di * acc.w + b.w, 0.f);

    if (LAYER == 1) {
        __half2 ha = __floats2half2_rn(h0, h1);
        __half2 hb = __floats2half2_rn(h2, h3);
        uint2 pk;
        pk.x = *reinterpret_cast<uint32_t*>(&ha);
        pk.y = *reinterpret_cast<uint32_t*>(&hb);
        reinterpret_cast<uint2*>(g_hh)[(size_t)n * 32 + l] = pk;
    } else {
        float4 wl = __ldg(reinterpret_cast<const float4*>(Wl) + l);
        float s = h0 * wl.x + h1 * wl.y + h2 * wl.z + h3 * wl.w;
        #pragma unroll
        for (int off = 16; off; off >>= 1) s += __shfl_xor_sync(0xffffffffu, s, off);
        if (l == 0) atomicAdd(&g_pool[__ldg(&batch[n])], s);
    }
}

__global__ void __launch_bounds__(256) out_kernel(float* __restrict__ out,
                                                  const float* __restrict__ bl) {
    int g = blockIdx.x * blockDim.x + threadIdx.x;
    if (g < N_GRAPHS) out[g] = g_pool[g] / fmaxf(g_cnt[g], 1.0f) + bl[0];
}

// ---------------------------------------------------------------------------
extern "C" void kernel_launch(void* const* d_in, const int* in_sizes, int n_in,
                              void* d_out, int out_size) {
    const float* x     = (const float*)d_in[0];
    const int*   ei    = (const int*)  d_in[1];
    const int*   batch = (const int*)  d_in[2];
    const float* W1    = (const float*)d_in[3];
    const float* b1    = (const float*)d_in[4];
    const float* W2    = (const float*)d_in[5];
    const float* b2    = (const float*)d_in[6];
    const float* Wl    = (const float*)d_in[7];
    const float* bl    = (const float*)d_in[8];
    const int* src = ei;
    const int* dst = ei + N_EDGES;

    cudaFuncSetAttribute(gemm_tc<0>, cudaFuncAttributeMaxDynamicSharedMemorySize,
                         GEMM_TC_SMEM);
    cudaFuncSetAttribute(gemm_tc<1>, cudaFuncAttributeMaxDynamicSharedMemorySize,
                         GEMM_TC_SMEM);

    const int ZB   = (N_NODES + 255) / 256;
    const int EB   = (N_EDGES + 255) / 256;
    const int TCB  = (N_NODES + 127) / 128;   // 391
    const int AGB  = (N_NODES * 32 + 255) / 256;

    // --- graph structure (shared by both layers) ---
    zero_kernel<<<ZB, 256>>>();
    deg_kernel<<<EB, 256>>>(dst);
    scan_k1<<<SCAN_NB, SCAN_BS>>>(batch);
    scan_k2<<<1, 128>>>();
    scan_k3<<<SCAN_NB, SCAN_BS>>>();
    fill_kernel<<<EB, 256>>>(src, dst);

    // --- layer 1 ---
    gemm_tc<0><<<TCB, 256, GEMM_TC_SMEM>>>(x, W1);
    agg_kernel<1><<<AGB, 256>>>(b1, nullptr, nullptr);

    // --- layer 2 (epilogue + Wl dot + pooling fused) ---
    gemm_tc<1><<<TCB, 256, GEMM_TC_SMEM>>>(nullptr, W2);
    agg_kernel<2><<<AGB, 256>>>(b2, Wl, batch);

    out_kernel<<<(N_GRAPHS + 255) / 256, 256>>>((float*)d_out, bl);
}